// round 16
// baseline (speedup 1.0000x reference)
#include <cuda_runtime.h>

// HONU degree-3: out[r] = sum_{a<=b<=c} w(a,b,c) * xs[a][r]*xs[b][r]*xs[c][r]
// xs[0][r]=1 (bias). Weight index = lexicographic rank (closed form); the
// comb_idx input is redundant and ignored.
//
// Pair factorization: s_ab[r] = sum_c w_abc * xs[c][r];
//                     out[r] += xs[a][r]*xs[b][r]*s_ab[r].
// FOUR 'a'-streams share each xs[c] LDS.128; warp owns all 256 rows (8 rows/
// thread = 4x packed fma.rn.f32x2). NEW vs R10/R13: weights are staged with
// cp.async (LDGSTS) -> smem, double-buffered 8-c-step chunks. cp.async holds
// NO registers and has no consumer dep until wait_group, so ptxas cannot
// serialize the loads into the FMA chain (the R10-R13 pathology: regs pinned
// at cap, loads issued lazily, ~260cyc exposed per load).
// Grid=148 (1 wave), 512 thr. Parallel per-row reduce kernel (R14).

#define NFEAT 129
#define NROW  256
#define NBLK  148
#define WPB   16
#define NRANGE (NBLK * WPB)   // 2368 ranges, one warp each (full 256 rows)

__host__ __device__ __forceinline__ int c2i(int v) { return v * (v - 1) / 2; }
__host__ __device__ __forceinline__ int c3i(int v) { return v * (v - 1) * (v - 2) / 6; }

// flat lexicographic rank of combo (a, b, b); total combos = C(131,3) = 366145
__device__ __forceinline__ int comb_base(int a, int b) {
    return 366145 - c3i(131 - a) + c2i(130 - a) - c2i(130 - b);
}

// total c-steps over all (b, quartet) rows: sum_b (b/4+1)*(129-b)
constexpr int t4_calc() {
    int t = 0;
    for (int b = 0; b < NFEAT; b++) t += (b / 4 + 1) * (NFEAT - b);
    return t;
}
constexpr int T4 = t4_calc();

__device__ float g_partial[NBLK * NROW];

__device__ __forceinline__ unsigned long long pack2(float w) {
    unsigned long long r;
    unsigned int wi = __float_as_uint(w);
    asm("mov.b64 %0, {%1, %1};" : "=l"(r) : "r"(wi));
    return r;
}
__device__ __forceinline__ void fma2(unsigned long long& d, unsigned long long a,
                                     unsigned long long b) {
    asm("fma.rn.f32x2 %0, %1, %2, %0;" : "+l"(d) : "l"(a), "l"(b));
}
__device__ __forceinline__ unsigned long long mul2(unsigned long long a,
                                                   unsigned long long b) {
    unsigned long long d;
    asm("mul.rn.f32x2 %0, %1, %2;" : "=l"(d) : "l"(a), "l"(b));
    return d;
}
__device__ __forceinline__ void cp_async4(unsigned int smem_addr,
                                          const float* gptr) {
    asm volatile("cp.async.ca.shared.global [%0], [%1], 4;\n"
                 :: "r"(smem_addr), "l"(gptr));
}
__device__ __forceinline__ void cp_commit() {
    asm volatile("cp.async.commit_group;\n");
}
__device__ __forceinline__ void cp_wait1() {
    asm volatile("cp.async.wait_group 1;\n");
}
__device__ __forceinline__ void cp_wait0() {
    asm volatile("cp.async.wait_group 0;\n");
}

__global__ void __launch_bounds__(512, 1)
honu_main(const float* __restrict__ x, const float* __restrict__ w) {
    extern __shared__ float smem[];
    float* xs   = smem;                   // [129][256] feature-major
    float* obuf = smem + NFEAT * NROW;    // [16][256] per-warp partials
    float* wst  = obuf + WPB * NROW;      // [16][2][32] staged weight chunks
    __shared__ int sP4[130];              // prefix of c-steps before feature b

    int tid = threadIdx.x;

    // ---- prefix table ----
    if (tid < 130) {
        int p = 0;
        for (int bb = 0; bb < tid && bb < NFEAT; bb++)
            p += (bb / 4 + 1) * (NFEAT - bb);
        sP4[tid] = p;                     // sP4[129] == T4
    }

    // ---- x transposed into smem (both 256-thread halves do 64 features) ----
    {
        int r = tid & 255, h = tid >> 8;
        const float4* xg = (const float4*)(x + (size_t)r * 128 + h * 64);
#pragma unroll
        for (int k = 0; k < 16; k++) {
            float4 v = xg[k];
            int f = h * 64 + 4 * k;
            xs[(f + 1) * NROW + r] = v.x;
            xs[(f + 2) * NROW + r] = v.y;
            xs[(f + 3) * NROW + r] = v.z;
            xs[(f + 4) * NROW + r] = v.w;
        }
        if (h == 0) xs[r] = 1.0f;         // bias feature
    }
    __syncthreads();

    int warp = tid >> 5, lane = tid & 31;
    int range = blockIdx.x * WPB + warp;
    int st = lane & 3;                    // staging: which stream this lane loads
    int u8 = lane >> 2;                   // staging: step within chunk (0..7)
    float* wsw = wst + warp * 64;         // this warp's two 32-float buffers
    unsigned int wsw_base =
        (unsigned int)__cvta_generic_to_shared(wsw + u8 * 4 + st);

    int s = (int)(((long long)T4 * range) / NRANGE);
    int e = (int)(((long long)T4 * (range + 1)) / NRANGE);

    // ---- decode start -> (b, quartet o, c-offset) via binary search ----
    int lo = 0, hi = NFEAT - 1;
    while (lo < hi) {                     // largest b with sP4[b] <= s
        int mid = (lo + hi + 1) >> 1;
        if (sP4[mid] <= s) lo = mid; else hi = mid - 1;
    }
    int b = lo;
    int rem = s - sP4[b];
    int L = NFEAT - b;
    int o = rem / L;
    int coff = rem % L;
    int pos = s;

    unsigned long long ov[4] = {0, 0, 0, 0};        // 8 rows as 4x f32x2
    const ulonglong2* xs2 = (const ulonglong2*)xs;  // 64 16B-quads per feature

    while (pos < e) {
        L = NFEAT - b;
        int a0 = o << 2;
        int na = b + 1 - a0;
        if (na > 4) na = 4;
        int seg = L - coff;
        if (seg > e - pos) seg = e - pos;

        // this lane's staging stream base (dead streams alias stream 0)
        int aj = (st < na) ? (a0 + st) : a0;
        const float* wlane = w + comb_base(aj, b) + coff;
        int maxi = L - 1 - coff;          // max valid in-bounds step offset

        unsigned long long acc[4][4];
#pragma unroll
        for (int j = 0; j < 4; j++) {
            acc[j][0] = 0; acc[j][1] = 0; acc[j][2] = 0; acc[j][3] = 0;
        }

        const ulonglong2* xp = xs2 + (size_t)(b + coff) * 64 + lane;
        const float4* wb0 = (const float4*)wsw;      // buffer 0: chunks even
        const float4* wb1 = (const float4*)(wsw + 32);

        // one c-step: 1 LDS.128 weights (4 streams) + 2 LDS.128 x + 16 fma2
        auto consume = [&](const float4* cur, int u) {
            float4 w4 = cur[u];
            ulonglong2 x0 = xp[0];
            ulonglong2 x1 = xp[32];
            xp += 64;
            unsigned long long w2;
            w2 = pack2(w4.x);
            fma2(acc[0][0], w2, x0.x); fma2(acc[0][1], w2, x0.y);
            fma2(acc[0][2], w2, x1.x); fma2(acc[0][3], w2, x1.y);
            w2 = pack2(w4.y);
            fma2(acc[1][0], w2, x0.x); fma2(acc[1][1], w2, x0.y);
            fma2(acc[1][2], w2, x1.x); fma2(acc[1][3], w2, x1.y);
            w2 = pack2(w4.z);
            fma2(acc[2][0], w2, x0.x); fma2(acc[2][1], w2, x0.y);
            fma2(acc[2][2], w2, x1.x); fma2(acc[2][3], w2, x1.y);
            w2 = pack2(w4.w);
            fma2(acc[3][0], w2, x0.x); fma2(acc[3][1], w2, x0.y);
            fma2(acc[3][2], w2, x1.x); fma2(acc[3][3], w2, x1.y);
        };

        // ---- stage chunk 0 (clamped in-bounds; masked at consume) ----
        {
            int idx = (u8 > maxi) ? maxi : u8;
            cp_async4(wsw_base, wlane + idx);
            cp_commit();
        }

        int nG = (seg + 7) >> 3;
        for (int g = 0; g < nG; g++) {
            if (g + 1 < nG) {             // stage chunk g+1 into other buffer
                int idx = 8 * (g + 1) + u8;
                if (idx > maxi) idx = maxi;
                cp_async4(wsw_base + ((g + 1) & 1) * 128, wlane + idx);
                cp_commit();
                cp_wait1();               // chunk g landed
            } else {
                cp_wait0();
            }
            __syncwarp();                 // visibility across lanes
            const float4* cur = (g & 1) ? wb1 : wb0;
            int n = seg - 8 * g;
            if (n >= 8) {
#pragma unroll
                for (int u = 0; u < 8; u++) consume(cur, u);
            } else {
#pragma unroll
                for (int u = 0; u < 8; u++)
                    if (u < n) consume(cur, u);
            }
            __syncwarp();                 // consume done before buffer reuse
        }

        // epilogue: out += (x_a * x_b) * s_ab  (linearity allows partial runs)
        {
            const ulonglong2* xbp = xs2 + (size_t)b * 64 + lane;
            ulonglong2 xb0v = xbp[0];
            ulonglong2 xb1v = xbp[32];
#pragma unroll
            for (int j = 0; j < 4; j++) {
                if (j < na) {
                    const ulonglong2* xap = xs2 + (size_t)(a0 + j) * 64 + lane;
                    ulonglong2 xa0 = xap[0];
                    ulonglong2 xa1 = xap[32];
                    fma2(ov[0], mul2(xa0.x, xb0v.x), acc[j][0]);
                    fma2(ov[1], mul2(xa0.y, xb0v.y), acc[j][1]);
                    fma2(ov[2], mul2(xa1.x, xb1v.x), acc[j][2]);
                    fma2(ov[3], mul2(xa1.y, xb1v.y), acc[j][3]);
                }
            }
        }

        pos += seg;
        coff += seg;
        if (coff == L) {
            coff = 0;
            o++;
            if ((o << 2) > b) { o = 0; b++; }
        }
    }

    // ---- per-warp partials -> smem, block combine -> global partial ----
    {
        float4* ob = (float4*)(obuf + warp * NROW);
        union { unsigned long long q[2]; float4 f; } u;
        u.q[0] = ov[0]; u.q[1] = ov[1];
        ob[lane] = u.f;                   // rows 4*lane .. 4*lane+3
        u.q[0] = ov[2]; u.q[1] = ov[3];
        ob[lane + 32] = u.f;              // rows 128+4*lane ..
    }
    __syncthreads();
    if (tid < NROW) {
        float ssum = 0.0f;
#pragma unroll
        for (int k = 0; k < WPB; k++) ssum += obuf[k * NROW + tid];
        g_partial[blockIdx.x * NROW + tid] = ssum;
    }
}

// One block per row; 128 threads; each thread sums <=2 partials, then
// warp-shuffle + smem tree reduce. Fully parallel.
__global__ void __launch_bounds__(128, 8)
honu_reduce(float* __restrict__ out) {
    __shared__ float wsum[4];
    int r = blockIdx.x;                   // row
    int tid = threadIdx.x;

    float v = 0.0f;
    if (tid < NBLK) v = g_partial[tid * NROW + r];
    if (tid + 128 < NBLK) v += g_partial[(tid + 128) * NROW + r];

#pragma unroll
    for (int d = 16; d > 0; d >>= 1)
        v += __shfl_down_sync(0xFFFFFFFFu, v, d);
    if ((tid & 31) == 0) wsum[tid >> 5] = v;
    __syncthreads();
    if (tid == 0)
        out[r] = (wsum[0] + wsum[1]) + (wsum[2] + wsum[3]);
}

extern "C" void kernel_launch(void* const* d_in, const int* in_sizes, int n_in,
                              void* d_out, int out_size) {
    (void)in_sizes; (void)n_in; (void)out_size;
    const float* x = (const float*)d_in[0];
    const float* w = (const float*)d_in[1];
    // d_in[2] (comb_idx) intentionally unused: lexicographic rank is closed-form.

    size_t smem_bytes =
        (size_t)(NFEAT * NROW + WPB * NROW + WPB * 64) * sizeof(float);  // 152,576 B
    cudaFuncSetAttribute(honu_main, cudaFuncAttributeMaxDynamicSharedMemorySize,
                         (int)smem_bytes);
    honu_main<<<NBLK, 512, smem_bytes>>>(x, w);
    honu_reduce<<<NROW, 128>>>((float*)d_out);
}